// round 7
// baseline (speedup 1.0000x reference)
#include <cuda_runtime.h>
#include <cstdint>
#include <cstddef>

// GroupedLinearsAdvanced: out[b,o,d] = sum_i x[b,i,d] * W[d,i,o] + bias[d,o]
//   x:    [16, 128, 4096] fp32
//   W:    [4096, 128, 128] fp32   (256 MB, streamed once -> HBM bound)
//   bias: [4096, 128] fp32
//   out:  [16, 128, 4096] fp32
//
// R6: occupancy push. Two warps per d-channel, each owning 64 of 128
// outputs -> accumulators halve to 32 regs, kernel fits 80 regs, giving
// 3 CTAs x 256 thr = 24 warps/SM (was 16 at 128 regs). W DRAM traffic is
// unchanged (o-split, not b-split). Inner f32x2 math and layouts kept.

#define B_SZ     16
#define IN_D     128
#define OUT_D    128
#define D_TOT    4096
#define D_TILE   4
#define THREADS  256
#define PF_DEPTH 4
#define XS_STRIDE 72                       // floats per i-row: 4*16 + 8 pad
#define SMEM_FLOATS (IN_D * XS_STRIDE)     // 9216 floats = 36864 B
#define SMEM_BYTES  (SMEM_FLOATS * 4)

__global__ void __launch_bounds__(THREADS, 3)
grouped_linears_kernel(const float* __restrict__ x,
                       const float* __restrict__ W,
                       const float* __restrict__ bias,
                       float* __restrict__ out)
{
    extern __shared__ float sm[];   // phase 1: x tile   phase 2: out transpose

    const int tid   = threadIdx.x;
    const int warp  = tid >> 5;        // 0..7
    const int lane  = tid & 31;
    const int dd    = warp >> 1;       // d-channel within tile: 0..3
    const int half  = warp & 1;        // o-half: 0 -> o<64, 1 -> o>=64
    const int d0    = blockIdx.x * D_TILE;
    const int d     = d0 + dd;
    const int obase = 64 * half + 2 * lane;   // this lane's first o

    // W[d][i][obase] as float2; each i advances 128 floats = 64 float2.
    // Kick the prefetch off FIRST so W is in flight during x staging.
    const float2* wp =
        reinterpret_cast<const float2*>(W + (size_t)d * IN_D * OUT_D) + (obase >> 1);
    float2 wbuf[PF_DEPTH];
#pragma unroll
    for (int s = 0; s < PF_DEPTH; ++s) wbuf[s] = __ldcs(wp + s * 64);

    // bias early too
    float2 bv = *reinterpret_cast<const float2*>(bias + (size_t)d * OUT_D + obase);

    // ---------------- Phase 0: load x tile ----------------
    // sm[i*XS_STRIDE + c*16 + b] = x[b][i][d0+c]; 8 float4 per thread.
#pragma unroll
    for (int r = 0; r < 8; ++r) {
        int p = tid + r * THREADS;      // 0..2047
        int i = p >> 4;
        int b = p & 15;
        float4 v = *reinterpret_cast<const float4*>(
            x + ((size_t)b * IN_D + i) * D_TOT + d0);
        float* row = &sm[i * XS_STRIDE + b];
        row[0 * 16] = v.x; row[1 * 16] = v.y; row[2 * 16] = v.z; row[3 * 16] = v.w;
    }
    __syncthreads();

    // ---------------- Phase 1: main GEMM loop ----------------
    // acc2[k][j]: packed f32x2 accumulator for (b=2k lo, b=2k+1 hi), o = obase + j.
    unsigned long long acc2[8][2];
    {
        float bj[2] = {bv.x, bv.y};
#pragma unroll
        for (int j = 0; j < 2; ++j) {
            unsigned long long pk;
            asm("mov.b64 %0, {%1, %1};" : "=l"(pk) : "f"(bj[j]));
#pragma unroll
            for (int k = 0; k < 8; ++k) acc2[k][j] = pk;
        }
    }

#pragma unroll 4
    for (int i = 0; i < IN_D; ++i) {
        // consume slot, immediately re-fill it PF_DEPTH iterations ahead
        float2 wcur = wbuf[i & (PF_DEPTH - 1)];
        int ipf = i + PF_DEPTH;
        if (ipf < IN_D) wbuf[i & (PF_DEPTH - 1)] = __ldcs(wp + ipf * 64);

        // x pairs for this (i, d): 16 floats = 4x LDS.128, all lanes broadcast
        const double2* xr =
            reinterpret_cast<const double2*>(&sm[i * XS_STRIDE + dd * 16]);
        double2 a0 = xr[0], a1 = xr[1], a2 = xr[2], a3 = xr[3];
        unsigned long long x2[8];
        x2[0] = __double_as_longlong(a0.x); x2[1] = __double_as_longlong(a0.y);
        x2[2] = __double_as_longlong(a1.x); x2[3] = __double_as_longlong(a1.y);
        x2[4] = __double_as_longlong(a2.x); x2[5] = __double_as_longlong(a2.y);
        x2[6] = __double_as_longlong(a3.x); x2[7] = __double_as_longlong(a3.y);

        // duplicate W scalars into both f32x2 halves
        unsigned long long wd[2];
        asm("mov.b64 %0, {%1, %1};" : "=l"(wd[0]) : "f"(wcur.x));
        asm("mov.b64 %0, {%1, %1};" : "=l"(wd[1]) : "f"(wcur.y));

#pragma unroll
        for (int k = 0; k < 8; ++k) {
#pragma unroll
            for (int j = 0; j < 2; ++j) {
                asm("fma.rn.f32x2 %0, %1, %2, %0;"
                    : "+l"(acc2[k][j]) : "l"(x2[k]), "l"(wd[j]));
            }
        }
    }

    // ---------------- Phase 2: transpose through smem ----------------
    __syncthreads();   // done reading x tile
    // outs[c][b*128 + o]; this warp writes o = obase, obase+1 for all 16 b.
    // Per-warp store addresses are 8B-stride contiguous -> conflict-free.
    float* outs = sm;
#pragma unroll
    for (int k = 0; k < 8; ++k) {
        float lo0, hi0, lo1, hi1;
        asm("mov.b64 {%0, %1}, %2;" : "=f"(lo0), "=f"(hi0) : "l"(acc2[k][0]));
        asm("mov.b64 {%0, %1}, %2;" : "=f"(lo1), "=f"(hi1) : "l"(acc2[k][1]));
        float2* p0 = reinterpret_cast<float2*>(
            &outs[dd * 2048 + (2 * k) * 128 + obase]);
        float2* p1 = reinterpret_cast<float2*>(
            &outs[dd * 2048 + (2 * k + 1) * 128 + obase]);
        *p0 = make_float2(lo0, lo1);
        *p1 = make_float2(hi0, hi1);
    }
    __syncthreads();

    // ---------------- Phase 3: coalesced global store ----------------
    // Each (b,o) pair p gets a 4-float d-contiguous run (one float4; the
    // adjacent-d0 CTA fills the sector's other half, merged in L2).
#pragma unroll
    for (int r = 0; r < 2; ++r) {
        int p4 = 4 * (tid + r * THREADS);   // groups of 4 consecutive p
        float v[D_TILE][4];
#pragma unroll
        for (int c = 0; c < D_TILE; ++c) {
            float4 t4 = *reinterpret_cast<float4*>(&outs[c * 2048 + p4]);
            v[c][0] = t4.x; v[c][1] = t4.y; v[c][2] = t4.z; v[c][3] = t4.w;
        }
#pragma unroll
        for (int pp = 0; pp < 4; ++pp) {
            int p = p4 + pp;            // p = b*128 + o
            float* op = out + (size_t)p * D_TOT + d0;
            *reinterpret_cast<float4*>(op) =
                make_float4(v[0][pp], v[1][pp], v[2][pp], v[3][pp]);
        }
    }
}

extern "C" void kernel_launch(void* const* d_in, const int* in_sizes, int n_in,
                              void* d_out, int out_size)
{
    (void)in_sizes; (void)n_in; (void)out_size;
    const float* x    = (const float*)d_in[0];
    const float* W    = (const float*)d_in[1];
    const float* bias = (const float*)d_in[2];
    float*       out  = (float*)d_out;

    // Idempotent, host-side, not a stream op: safe under graph capture.
    cudaFuncSetAttribute(grouped_linears_kernel,
                         cudaFuncAttributeMaxDynamicSharedMemorySize, SMEM_BYTES);

    grouped_linears_kernel<<<D_TOT / D_TILE, THREADS, SMEM_BYTES>>>(x, W, bias, out);
}